// round 7
// baseline (speedup 1.0000x reference)
#include <cuda_runtime.h>
#include <cuda_fp16.h>
#include <cstdint>

// Mean-shift as unnormalized attention, single persistent kernel (f16 path).
//   S = (sX)^T (sX), s^2 = 2*log2(e)  =>  P = ex2(S) = exp(2*x_i.x_j)
//   deg = rowsum(P) via FADD on fma pipe;  O = P @ V (tensor)
//   Xnew = eta*O/deg + (1-eta)X
// 2x2 warp tiling; 3-stage cp.async pipeline, ONE __syncthreads per tile.

#define NPTS   9216
#define DIM    32
#define ETA    0.5f
#define SCALE  1.6986436f          // sqrt(2*log2(e))
#define TJ     64
#define TI     64
#define KSPLIT 4
#define JT     (NPTS / TJ)             // 144
#define NT     (NPTS / (TI * KSPLIT))  // 36 tiles per split
#define GRID   (JT * KSPLIT)           // 576
#define FRAME  (DIM * NPTS)

#define KST 80      // key row stride bytes (32 f16 + pad)
#define VST 144     // v row stride bytes (64 f16 + pad)

#define KBUF 5120               // TI * KST
#define VBUF 4608               // DIM * VST
#define SH_K 0                  // 3 x 5120 = 15360
#define SH_V (3 * KBUF)         // 3 x 4608 = 13824
#define SH_X 0                  // O exchange (8KB), aliases K staging
#define SH_XD 8192              // deg exchange (2KB)
#define SMEM_BYTES (3 * KBUF + 3 * VBUF)   // 29184

__device__ __align__(16) __half g_s[NPTS * DIM];  // [i][d], scaled, f16
__device__ __align__(16) __half g_v[DIM * NPTS];  // [d][i], f16
__device__ float g_accum[KSPLIT][DIM][NPTS];
__device__ float g_degp[KSPLIT][NPTS];
__device__ unsigned g_bar;
__device__ unsigned g_fin;

// ---------------- helpers ----------------
__device__ __forceinline__ uint32_t smem_u32(const void* p) {
    uint32_t a;
    asm("{ .reg .u64 t; cvta.to.shared.u64 t, %1; cvt.u32.u64 %0, t; }" : "=r"(a) : "l"(p));
    return a;
}
__device__ __forceinline__ void ldsm4(uint32_t* r, uint32_t a) {
    asm volatile("ldmatrix.sync.aligned.m8n8.x4.shared.b16 {%0,%1,%2,%3}, [%4];"
        : "=r"(r[0]), "=r"(r[1]), "=r"(r[2]), "=r"(r[3]) : "r"(a));
}
__device__ __forceinline__ void mma16816(float* c, const uint32_t* a,
                                         uint32_t b0, uint32_t b1) {
    asm volatile("mma.sync.aligned.m16n8k16.row.col.f32.f16.f16.f32 "
        "{%0,%1,%2,%3}, {%4,%5,%6,%7}, {%8,%9}, {%0,%1,%2,%3};"
        : "+f"(c[0]), "+f"(c[1]), "+f"(c[2]), "+f"(c[3])
        : "r"(a[0]), "r"(a[1]), "r"(a[2]), "r"(a[3]), "r"(b0), "r"(b1));
}
__device__ __forceinline__ uint32_t cvt_f16x2(float lo, float hi) {
    uint32_t r;
    asm("cvt.rn.f16x2.f32 %0, %1, %2;" : "=r"(r) : "f"(hi), "f"(lo));
    return r;
}
__device__ __forceinline__ uint32_t ex2_h2(uint32_t x) {
    uint32_t y;
    asm("ex2.approx.f16x2 %0, %1;" : "=r"(y) : "r"(x));
    return y;
}
#define CP16(dst, src) asm volatile("cp.async.cg.shared.global [%0], [%1], 16;" :: "r"(dst), "l"(src) : "memory")
#define CP_COMMIT()    asm volatile("cp.async.commit_group;" ::: "memory")
#define CP_WAIT0()     asm volatile("cp.async.wait_group 0;" ::: "memory")
#define CP_WAIT1()     asm volatile("cp.async.wait_group 1;" ::: "memory")

__device__ __forceinline__ void grid_bar(unsigned tgt) {
    __syncthreads();
    __threadfence();
    if (threadIdx.x == 0) {
        atomicAdd(&g_bar, 1u);
        while (*(volatile unsigned*)&g_bar < tgt) __nanosleep(32);
    }
    __syncthreads();
}

// Stage one 64-key K/V tile via cp.async (.cg: L2-only, avoids stale L1).
__device__ __forceinline__ void stage_tiles(uint32_t kdst, uint32_t vdst,
                                            int i0, int tid) {
    const char* ks = reinterpret_cast<const char*>(g_s) + (size_t)i0 * (DIM * 2);
#pragma unroll
    for (int v = 0; v < 2; v++) {
        int idx = v * 128 + tid, row = idx >> 2, c = idx & 3;
        CP16(kdst + row * KST + c * 16, ks + row * 64 + c * 16);
    }
    const char* vs = reinterpret_cast<const char*>(g_v) + (size_t)i0 * 2;
#pragma unroll
    for (int v = 0; v < 2; v++) {
        int idx = v * 128 + tid, row = idx >> 3, c = idx & 7;
        CP16(vdst + row * VST + c * 16, vs + (size_t)row * (NPTS * 2) + c * 16);
    }
}

__global__ void __launch_bounds__(128, 4)
ms_persist(const float* __restrict__ x_in, float* __restrict__ out) {
    __shared__ __align__(16) uint8_t sm[SMEM_BYTES];

    const int tid = threadIdx.x, w = tid >> 5, lane = tid & 31;
    const int wq = w >> 1, wk = w & 1;
    const int jt = blockIdx.x, split = blockIdx.y;
    const unsigned gid = (blockIdx.y * JT + blockIdx.x) * 128u + tid;
    const uint32_t smbase = smem_u32(sm);
    unsigned tgt = 0;

    // ---------------- phase 0: init (4 threads per pixel) ----------------
    if (gid < NPTS * 4u) {
        const int j = gid >> 2, d0 = (gid & 3) * 8;
        uint32_t pk[4];
#pragma unroll
        for (int q = 0; q < 4; q++) {
            int d = d0 + q * 2;
            float x0 = x_in[d * NPTS + j];
            float x1 = x_in[(d + 1) * NPTS + j];
            out[d * NPTS + j] = x0;
            out[(d + 1) * NPTS + j] = x1;
            g_v[d * NPTS + j] = __float2half(x0);
            g_v[(d + 1) * NPTS + j] = __float2half(x1);
            pk[q] = cvt_f16x2(x0 * SCALE, x1 * SCALE);
        }
        *reinterpret_cast<uint4*>(g_s + j * DIM + d0) =
            make_uint4(pk[0], pk[1], pk[2], pk[3]);
    }
    tgt += GRID; grid_bar(tgt);

    // hoisted ldsm addresses (buffer 0; add buf*KBUF / buf*VBUF)
    uint32_t ka0[4], va0[4];
#pragma unroll
    for (int nt = 0; nt < 4; nt++)
        ka0[nt] = smbase + SH_K + (wk * 32 + nt * 8 + (lane & 7)) * KST + (lane >> 3) * 16;
#pragma unroll
    for (int dt = 0; dt < 4; dt++)
        va0[dt] = smbase + SH_V + (dt * 8 + (lane & 7)) * VST + (wk * 32 + (lane >> 3) * 8) * 2;

    for (int t = 0; t < 3; t++) {
        // ---------------- attention phase ----------------
        const int j0 = jt * TJ;
        {
            const uint4* src = reinterpret_cast<const uint4*>(g_s) + j0 * 4;
#pragma unroll
            for (int v = 0; v < 2; v++) {
                int idx = v * 128 + tid, row = idx >> 2, c = idx & 3;
                uint4 val = __ldcg(&src[row * 4 + c]);
                *reinterpret_cast<uint4*>(&sm[SH_K + row * KST + c * 16]) = val;
            }
        }
        __syncthreads();
        uint32_t qa[16];
        {
            int m = lane >> 3, r = lane & 7;
#pragma unroll
            for (int mt = 0; mt < 2; mt++) {
                uint32_t base = smbase + SH_K +
                    (wq * 32 + mt * 16 + (m & 1) * 8 + r) * KST + (m >> 1) * 16;
                ldsm4(qa + mt * 8, base);
                ldsm4(qa + mt * 8 + 4, base + 32);
            }
        }
        __syncthreads();

        float O[32];
#pragma unroll
        for (int i = 0; i < 32; i++) O[i] = 0.0f;
        float dg[4] = {0.0f, 0.0f, 0.0f, 0.0f};

        const int i00 = split * (NPTS / KSPLIT);
        stage_tiles(smbase + SH_K,        smbase + SH_V,        i00,      tid);
        CP_COMMIT();
        stage_tiles(smbase + SH_K + KBUF, smbase + SH_V + VBUF, i00 + TI, tid);
        CP_COMMIT();

        int buf = 0;
        for (int it = 0; it < NT; it++) {
            if (it + 1 < NT) { CP_WAIT1(); } else { CP_WAIT0(); }
            __syncthreads();
            if (it + 2 < NT) {
                int b2 = buf - 1; if (b2 < 0) b2 += 3;   // (it+2)%3
                stage_tiles(smbase + SH_K + b2 * KBUF, smbase + SH_V + b2 * VBUF,
                            i00 + (it + 2) * TI, tid);
                CP_COMMIT();
            }
            const uint32_t kofs = buf * KBUF, vofs = buf * VBUF;

            // preload all K fragments for this tile
            uint32_t kb[16];
#pragma unroll
            for (int nt = 0; nt < 4; nt++) ldsm4(kb + nt * 4, ka0[nt] + kofs);

            // GEMM1: S[2 x 16 rows][32 keys] = Q x K^T
            float s[32];
#pragma unroll
            for (int x = 0; x < 32; x++) s[x] = 0.0f;
#pragma unroll
            for (int nt = 0; nt < 4; nt++) {
                mma16816(&s[nt * 4],      qa,      kb[nt * 4 + 0], kb[nt * 4 + 1]);
                mma16816(&s[nt * 4],      qa + 4,  kb[nt * 4 + 2], kb[nt * 4 + 3]);
                mma16816(&s[16 + nt * 4], qa + 8,  kb[nt * 4 + 0], kb[nt * 4 + 1]);
                mma16816(&s[16 + nt * 4], qa + 12, kb[nt * 4 + 2], kb[nt * 4 + 3]);
            }

            // preload all V fragments
            uint32_t vb[16];
#pragma unroll
            for (int dt = 0; dt < 4; dt++) ldsm4(vb + dt * 4, va0[dt] + vofs);

            // P = ex2(S) as f16x2 pairs -> A-fragments for GEMM2
            uint32_t pf[16];
#pragma unroll
            for (int mt = 0; mt < 2; mt++) {
#pragma unroll
                for (int kh = 0; kh < 2; kh++) {
                    const float* sa = &s[mt * 16 + kh * 8];
                    uint32_t* pa = &pf[mt * 8 + kh * 4];
                    pa[0] = ex2_h2(cvt_f16x2(sa[0], sa[1]));
                    pa[1] = ex2_h2(cvt_f16x2(sa[2], sa[3]));
                    pa[2] = ex2_h2(cvt_f16x2(sa[4], sa[5]));
                    pa[3] = ex2_h2(cvt_f16x2(sa[6], sa[7]));
                }
            }

            // deg partial sums on fma pipe (exact same P values via s)
            // NOTE: deg must sum P (f16-rounded), not raw exp(s): use f16->f32 of pf.
#pragma unroll
            for (int mt = 0; mt < 2; mt++) {
#pragma unroll
                for (int nt = 0; nt < 4; nt++) {
                    const uint32_t* pa = &pf[mt * 8 + (nt >> 1) * 4 + (nt & 1) * 2];
                    __half2 h0 = *reinterpret_cast<const __half2*>(&pa[0]);
                    __half2 h1 = *reinterpret_cast<const __half2*>(&pa[1]);
                    float2 f0 = __half22float2(h0);
                    float2 f1 = __half22float2(h1);
                    dg[mt * 2 + 0] += f0.x + f0.y;
                    dg[mt * 2 + 1] += f1.x + f1.y;
                }
            }

            // GEMM2: O[2 x 16 rows][32 d] += P x V
#pragma unroll
            for (int dt = 0; dt < 4; dt++) {
                mma16816(&O[dt * 4],      &pf[0],  vb[dt * 4 + 0], vb[dt * 4 + 1]);
                mma16816(&O[dt * 4],      &pf[4],  vb[dt * 4 + 2], vb[dt * 4 + 3]);
                mma16816(&O[16 + dt * 4], &pf[8],  vb[dt * 4 + 0], vb[dt * 4 + 1]);
                mma16816(&O[16 + dt * 4], &pf[12], vb[dt * 4 + 2], vb[dt * 4 + 3]);
            }
            buf++; if (buf == 3) buf = 0;
        }

        // quad-reduce deg (rows of an mma tile spread over 4 lanes)
#pragma unroll
        for (int q = 0; q < 4; q++) {
            dg[q] += __shfl_xor_sync(0xFFFFFFFFu, dg[q], 1);
            dg[q] += __shfl_xor_sync(0xFFFFFFFFu, dg[q], 2);
        }

        // ---- cross-warp (wk) reduction of O and deg via smem ----
        __syncthreads();   // all warps done with K/V buffers (SH_X aliases them)
        if (wk == 1) {
#pragma unroll
            for (int r4 = 0; r4 < 8; r4++)
                *reinterpret_cast<float4*>(&sm[SH_X + wq * 4096 + r4 * 512 + lane * 16]) =
                    make_float4(O[r4 * 4], O[r4 * 4 + 1], O[r4 * 4 + 2], O[r4 * 4 + 3]);
            *reinterpret_cast<float4*>(&sm[SH_XD + (wq * 32 + lane) * 16]) =
                make_float4(dg[0], dg[1], dg[2], dg[3]);
        }
        __syncthreads();
        if (wk == 0) {
#pragma unroll
            for (int r4 = 0; r4 < 8; r4++) {
                float4 pv = *reinterpret_cast<const float4*>(
                    &sm[SH_X + wq * 4096 + r4 * 512 + lane * 16]);
                O[r4 * 4]     += pv.x;
                O[r4 * 4 + 1] += pv.y;
                O[r4 * 4 + 2] += pv.z;
                O[r4 * 4 + 3] += pv.w;
            }
            float4 pd = *reinterpret_cast<const float4*>(&sm[SH_XD + (wq * 32 + lane) * 16]);
            dg[0] += pd.x; dg[1] += pd.y; dg[2] += pd.z; dg[3] += pd.w;

#pragma unroll
            for (int mt = 0; mt < 2; mt++) {
                const int jj = j0 + wq * 32 + mt * 16 + (lane >> 2);
#pragma unroll
                for (int dt = 0; dt < 4; dt++) {
                    int d0 = dt * 8 + 2 * (lane & 3);
                    g_accum[split][d0][jj]         = O[mt * 16 + dt * 4 + 0];
                    g_accum[split][d0 + 1][jj]     = O[mt * 16 + dt * 4 + 1];
                    g_accum[split][d0][jj + 8]     = O[mt * 16 + dt * 4 + 2];
                    g_accum[split][d0 + 1][jj + 8] = O[mt * 16 + dt * 4 + 3];
                }
                if ((lane & 3) == 0) {
                    g_degp[split][jj]     = dg[mt * 2 + 0];
                    g_degp[split][jj + 8] = dg[mt * 2 + 1];
                }
            }
        }
        tgt += GRID; grid_bar(tgt);

        // ---------------- reduce phase (4 threads per pixel) ----------------
        if (gid < NPTS * 4u) {
            const int j = gid >> 2, d0 = (gid & 3) * 8;
            float deg = 0.0f;
#pragma unroll
            for (int sp = 0; sp < KSPLIT; sp++) deg += __ldcg(&g_degp[sp][j]);
            const float inv = ETA / deg;
            const float* X  = out + (size_t)t * FRAME;
            float*       Xn = out + (size_t)(t + 1) * FRAME;
            uint32_t pk[4];
#pragma unroll
            for (int q = 0; q < 4; q++) {
                int d = d0 + q * 2;
                float a0 = 0.0f, a1 = 0.0f;
#pragma unroll
                for (int sp = 0; sp < KSPLIT; sp++) {
                    a0 += __ldcg(&g_accum[sp][d][j]);
                    a1 += __ldcg(&g_accum[sp][d + 1][j]);
                }
                float x0 = a0 * inv + (1.0f - ETA) * X[d * NPTS + j];
                float x1 = a1 * inv + (1.0f - ETA) * X[(d + 1) * NPTS + j];
                Xn[d * NPTS + j] = x0;
                Xn[(d + 1) * NPTS + j] = x1;
                if (t < 2) {
                    g_v[d * NPTS + j] = __float2half(x0);
                    g_v[(d + 1) * NPTS + j] = __float2half(x1);
                    pk[q] = cvt_f16x2(x0 * SCALE, x1 * SCALE);
                }
            }
            if (t < 2)
                *reinterpret_cast<uint4*>(g_s + j * DIM + d0) =
                    make_uint4(pk[0], pk[1], pk[2], pk[3]);
        }
        if (t < 2) { tgt += GRID; grid_bar(tgt); }
    }

    // ---------------- epilogue: counter reset handshake ----------------
    __syncthreads();
    __threadfence();
    if (tid == 0) atomicAdd(&g_fin, 1u);
    if (gid == 0) {
        while (*(volatile unsigned*)&g_fin < GRID) __nanosleep(64);
        *(volatile unsigned*)&g_bar = 0;
        *(volatile unsigned*)&g_fin = 0;
        __threadfence();
    }
}

extern "C" void kernel_launch(void* const* d_in, const int* in_sizes, int n_in,
                              void* d_out, int out_size) {
    const float* x_in = (const float*)d_in[0];
    float* out = (float*)d_out;
    dim3 grid(JT, KSPLIT);
    ms_persist<<<grid, 128>>>(x_in, out);
}

// round 8
// speedup vs baseline: 1.0696x; 1.0696x over previous
#include <cuda_runtime.h>
#include <cuda_fp16.h>
#include <cstdint>

// Mean-shift as unnormalized attention, single persistent kernel (f16 path).
//   S = (sX)^T (sX), s^2 = 2*log2(e)  =>  P = ex2(S) = exp(2*x_i.x_j)
//   deg = P @ ones (tensor-core mma, fp32 accum)
//   O = P @ V;  Xnew = eta*O/deg + (1-eta)X
// 2x2 warp tiling; 3-stage cp.async ring -> ONE __syncthreads per tile.

#define NPTS   9216
#define DIM    32
#define ETA    0.5f
#define SCALE  1.6986436f          // sqrt(2*log2(e))
#define TJ     64
#define TI     64
#define KSPLIT 4
#define JT     (NPTS / TJ)             // 144
#define NT     (NPTS / (TI * KSPLIT))  // 36 tiles per split
#define GRID   (JT * KSPLIT)           // 576
#define FRAME  (DIM * NPTS)

#define KST 80      // key row stride bytes (32 f16 + pad)
#define VST 144     // v row stride bytes (64 f16 + pad)
#define ONES2 0x3C003C00u

#define KBUF 5120               // TI * KST
#define VBUF 4608               // DIM * VST
#define SH_K 0                  // 3 x 5120 = 15360
#define SH_V (3 * KBUF)         // 3 x 4608 = 13824
#define SH_X 0                  // O exchange (8KB), aliases K staging
#define SH_XD 8192              // deg exchange (1KB)
#define SMEM_BYTES (3 * KBUF + 3 * VBUF)   // 29184

__device__ __align__(16) __half g_s[NPTS * DIM];  // [i][d], scaled, f16
__device__ __align__(16) __half g_v[DIM * NPTS];  // [d][i], f16
__device__ float g_accum[KSPLIT][DIM][NPTS];
__device__ float g_degp[KSPLIT][NPTS];
__device__ unsigned g_bar;
__device__ unsigned g_fin;

// ---------------- helpers ----------------
__device__ __forceinline__ uint32_t smem_u32(const void* p) {
    uint32_t a;
    asm("{ .reg .u64 t; cvta.to.shared.u64 t, %1; cvt.u32.u64 %0, t; }" : "=r"(a) : "l"(p));
    return a;
}
__device__ __forceinline__ void ldsm4(uint32_t* r, uint32_t a) {
    asm volatile("ldmatrix.sync.aligned.m8n8.x4.shared.b16 {%0,%1,%2,%3}, [%4];"
        : "=r"(r[0]), "=r"(r[1]), "=r"(r[2]), "=r"(r[3]) : "r"(a));
}
__device__ __forceinline__ void mma16816(float* c, const uint32_t* a,
                                         uint32_t b0, uint32_t b1) {
    asm volatile("mma.sync.aligned.m16n8k16.row.col.f32.f16.f16.f32 "
        "{%0,%1,%2,%3}, {%4,%5,%6,%7}, {%8,%9}, {%0,%1,%2,%3};"
        : "+f"(c[0]), "+f"(c[1]), "+f"(c[2]), "+f"(c[3])
        : "r"(a[0]), "r"(a[1]), "r"(a[2]), "r"(a[3]), "r"(b0), "r"(b1));
}
__device__ __forceinline__ uint32_t cvt_f16x2(float lo, float hi) {
    uint32_t r;
    asm("cvt.rn.f16x2.f32 %0, %1, %2;" : "=r"(r) : "f"(hi), "f"(lo));
    return r;
}
__device__ __forceinline__ uint32_t ex2_h2(uint32_t x) {
    uint32_t y;
    asm("ex2.approx.f16x2 %0, %1;" : "=r"(y) : "r"(x));
    return y;
}
#define CP16(dst, src) asm volatile("cp.async.cg.shared.global [%0], [%1], 16;" :: "r"(dst), "l"(src) : "memory")
#define CP_COMMIT()    asm volatile("cp.async.commit_group;" ::: "memory")
#define CP_WAIT0()     asm volatile("cp.async.wait_group 0;" ::: "memory")
#define CP_WAIT1()     asm volatile("cp.async.wait_group 1;" ::: "memory")

__device__ __forceinline__ void grid_bar(unsigned tgt) {
    __syncthreads();
    __threadfence();
    if (threadIdx.x == 0) {
        atomicAdd(&g_bar, 1u);
        while (*(volatile unsigned*)&g_bar < tgt) __nanosleep(32);
    }
    __syncthreads();
}

// Stage one 64-key K/V tile via cp.async (.cg: L2-only, avoids stale L1).
__device__ __forceinline__ void stage_tiles(uint32_t kdst, uint32_t vdst,
                                            int i0, int tid) {
    const char* ks = reinterpret_cast<const char*>(g_s) + (size_t)i0 * (DIM * 2);
#pragma unroll
    for (int v = 0; v < 2; v++) {
        int idx = v * 128 + tid, row = idx >> 2, c = idx & 3;
        CP16(kdst + row * KST + c * 16, ks + row * 64 + c * 16);
    }
    const char* vs = reinterpret_cast<const char*>(g_v) + (size_t)i0 * 2;
#pragma unroll
    for (int v = 0; v < 2; v++) {
        int idx = v * 128 + tid, row = idx >> 3, c = idx & 7;
        CP16(vdst + row * VST + c * 16, vs + (size_t)row * (NPTS * 2) + c * 16);
    }
}

__global__ void __launch_bounds__(128, 4)
ms_persist(const float* __restrict__ x_in, float* __restrict__ out) {
    __shared__ __align__(16) uint8_t sm[SMEM_BYTES];

    const int tid = threadIdx.x, w = tid >> 5, lane = tid & 31;
    const int wq = w >> 1, wk = w & 1;
    const int jt = blockIdx.x, split = blockIdx.y;
    const unsigned gid = (blockIdx.y * JT + blockIdx.x) * 128u + tid;
    const uint32_t smbase = smem_u32(sm);
    unsigned tgt = 0;

    // ---------------- phase 0: init (4 threads per pixel) ----------------
    if (gid < NPTS * 4u) {
        const int j = gid >> 2, d0 = (gid & 3) * 8;
        uint32_t pk[4];
#pragma unroll
        for (int q = 0; q < 4; q++) {
            int d = d0 + q * 2;
            float x0 = x_in[d * NPTS + j];
            float x1 = x_in[(d + 1) * NPTS + j];
            out[d * NPTS + j] = x0;
            out[(d + 1) * NPTS + j] = x1;
            g_v[d * NPTS + j] = __float2half(x0);
            g_v[(d + 1) * NPTS + j] = __float2half(x1);
            pk[q] = cvt_f16x2(x0 * SCALE, x1 * SCALE);
        }
        *reinterpret_cast<uint4*>(g_s + j * DIM + d0) =
            make_uint4(pk[0], pk[1], pk[2], pk[3]);
    }
    tgt += GRID; grid_bar(tgt);

    // hoisted ldsm addresses (buffer 0; add buf*KBUF / buf*VBUF)
    uint32_t ka0[4], va0[4];
#pragma unroll
    for (int nt = 0; nt < 4; nt++)
        ka0[nt] = smbase + SH_K + (wk * 32 + nt * 8 + (lane & 7)) * KST + (lane >> 3) * 16;
#pragma unroll
    for (int dt = 0; dt < 4; dt++)
        va0[dt] = smbase + SH_V + (dt * 8 + (lane & 7)) * VST + (wk * 32 + (lane >> 3) * 8) * 2;

    for (int t = 0; t < 3; t++) {
        // ---------------- attention phase ----------------
        const int j0 = jt * TJ;
        {
            const uint4* src = reinterpret_cast<const uint4*>(g_s) + j0 * 4;
#pragma unroll
            for (int v = 0; v < 2; v++) {
                int idx = v * 128 + tid, row = idx >> 2, c = idx & 3;
                uint4 val = __ldcg(&src[row * 4 + c]);
                *reinterpret_cast<uint4*>(&sm[SH_K + row * KST + c * 16]) = val;
            }
        }
        __syncthreads();
        // Q A-fragments: 2 mtiles (rows wq*32 + mt*16), k = 0..31
        uint32_t qa[16];
        {
            int m = lane >> 3, r = lane & 7;
#pragma unroll
            for (int mt = 0; mt < 2; mt++) {
                uint32_t base = smbase + SH_K +
                    (wq * 32 + mt * 16 + (m & 1) * 8 + r) * KST + (m >> 1) * 16;
                ldsm4(qa + mt * 8, base);
                ldsm4(qa + mt * 8 + 4, base + 32);
            }
        }
        __syncthreads();

        float O[32];
#pragma unroll
        for (int i = 0; i < 32; i++) O[i] = 0.0f;
        float dacc[8];
#pragma unroll
        for (int i = 0; i < 8; i++) dacc[i] = 0.0f;

        const int i00 = split * (NPTS / KSPLIT);
        stage_tiles(smbase + SH_K,        smbase + SH_V,        i00,      tid);
        CP_COMMIT();
        stage_tiles(smbase + SH_K + KBUF, smbase + SH_V + VBUF, i00 + TI, tid);
        CP_COMMIT();

        int buf = 0;
        for (int it = 0; it < NT; it++) {
            if (it + 1 < NT) { CP_WAIT1(); } else { CP_WAIT0(); }
            __syncthreads();
            if (it + 2 < NT) {
                int b2 = buf - 1; if (b2 < 0) b2 += 3;   // (it+2)%3
                stage_tiles(smbase + SH_K + b2 * KBUF, smbase + SH_V + b2 * VBUF,
                            i00 + (it + 2) * TI, tid);
                CP_COMMIT();
            }
            const uint32_t kofs = buf * KBUF, vofs = buf * VBUF;

            // GEMM1: S[2 x 16 rows][32 keys] = Q x K^T
            float s[32];
#pragma unroll
            for (int x = 0; x < 32; x++) s[x] = 0.0f;
#pragma unroll
            for (int nt = 0; nt < 4; nt++) {
                uint32_t kb[4];
                ldsm4(kb, ka0[nt] + kofs);
                mma16816(&s[nt * 4],      qa,      kb[0], kb[1]);
                mma16816(&s[nt * 4],      qa + 4,  kb[2], kb[3]);
                mma16816(&s[16 + nt * 4], qa + 8,  kb[0], kb[1]);
                mma16816(&s[16 + nt * 4], qa + 12, kb[2], kb[3]);
            }

            // P = ex2(S) as f16x2 pairs -> A-fragments for GEMM2
            uint32_t pf[16];
#pragma unroll
            for (int mt = 0; mt < 2; mt++) {
#pragma unroll
                for (int kh = 0; kh < 2; kh++) {
                    const float* sa = &s[mt * 16 + kh * 8];
                    uint32_t* pa = &pf[mt * 8 + kh * 4];
                    pa[0] = ex2_h2(cvt_f16x2(sa[0], sa[1]));
                    pa[1] = ex2_h2(cvt_f16x2(sa[2], sa[3]));
                    pa[2] = ex2_h2(cvt_f16x2(sa[4], sa[5]));
                    pa[3] = ex2_h2(cvt_f16x2(sa[6], sa[7]));
                }
            }

            // deg += P @ ones (fp32, tensor pipe, deterministic)
#pragma unroll
            for (int mt = 0; mt < 2; mt++) {
                mma16816(&dacc[mt * 4], &pf[mt * 8],     ONES2, ONES2);
                mma16816(&dacc[mt * 4], &pf[mt * 8 + 4], ONES2, ONES2);
            }

            // GEMM2: O[2 x 16 rows][32 d] += P x V  (V shared across mtiles)
#pragma unroll
            for (int dt = 0; dt < 4; dt++) {
                uint32_t vb[4];
                ldsm4(vb, va0[dt] + vofs);
                mma16816(&O[dt * 4],      &pf[0],  vb[0], vb[1]);
                mma16816(&O[dt * 4],      &pf[4],  vb[2], vb[3]);
                mma16816(&O[16 + dt * 4], &pf[8],  vb[0], vb[1]);
                mma16816(&O[16 + dt * 4], &pf[12], vb[2], vb[3]);
            }
            buf++; if (buf == 3) buf = 0;
        }

        // ---- cross-warp (wk) reduction of O and deg via smem ----
        __syncthreads();   // all warps done with K/V buffers (SH_X aliases them)
        if (wk == 1) {
#pragma unroll
            for (int r4 = 0; r4 < 8; r4++)
                *reinterpret_cast<float4*>(&sm[SH_X + wq * 4096 + r4 * 512 + lane * 16]) =
                    make_float4(O[r4 * 4], O[r4 * 4 + 1], O[r4 * 4 + 2], O[r4 * 4 + 3]);
            *reinterpret_cast<float2*>(&sm[SH_XD + wq * 512 + lane * 8]) =
                make_float2(dacc[0], dacc[2]);
            *reinterpret_cast<float2*>(&sm[SH_XD + wq * 512 + 256 + lane * 8]) =
                make_float2(dacc[4], dacc[6]);
        }
        __syncthreads();
        if (wk == 0) {
#pragma unroll
            for (int r4 = 0; r4 < 8; r4++) {
                float4 pv = *reinterpret_cast<const float4*>(
                    &sm[SH_X + wq * 4096 + r4 * 512 + lane * 16]);
                O[r4 * 4]     += pv.x;
                O[r4 * 4 + 1] += pv.y;
                O[r4 * 4 + 2] += pv.z;
                O[r4 * 4 + 3] += pv.w;
            }
            float2 p0 = *reinterpret_cast<const float2*>(&sm[SH_XD + wq * 512 + lane * 8]);
            float2 p1 = *reinterpret_cast<const float2*>(&sm[SH_XD + wq * 512 + 256 + lane * 8]);
            dacc[0] += p0.x; dacc[2] += p0.y;
            dacc[4] += p1.x; dacc[6] += p1.y;

#pragma unroll
            for (int mt = 0; mt < 2; mt++) {
                const int jj = j0 + wq * 32 + mt * 16 + (lane >> 2);
#pragma unroll
                for (int dt = 0; dt < 4; dt++) {
                    int d0 = dt * 8 + 2 * (lane & 3);
                    g_accum[split][d0][jj]         = O[mt * 16 + dt * 4 + 0];
                    g_accum[split][d0 + 1][jj]     = O[mt * 16 + dt * 4 + 1];
                    g_accum[split][d0][jj + 8]     = O[mt * 16 + dt * 4 + 2];
                    g_accum[split][d0 + 1][jj + 8] = O[mt * 16 + dt * 4 + 3];
                }
                if ((lane & 3) == 0) {
                    g_degp[split][jj]     = dacc[mt * 4 + 0];
                    g_degp[split][jj + 8] = dacc[mt * 4 + 2];
                }
            }
        }
        tgt += GRID; grid_bar(tgt);

        // ---------------- reduce phase (4 threads per pixel) ----------------
        if (gid < NPTS * 4u) {
            const int j = gid >> 2, d0 = (gid & 3) * 8;
            float deg = 0.0f;
#pragma unroll
            for (int sp = 0; sp < KSPLIT; sp++) deg += __ldcg(&g_degp[sp][j]);
            const float inv = ETA / deg;
            const float* X  = out + (size_t)t * FRAME;
            float*       Xn = out + (size_t)(t + 1) * FRAME;
            uint32_t pk[4];
#pragma unroll
            for (int q = 0; q < 4; q++) {
                int d = d0 + q * 2;
                float a0 = 0.0f, a1 = 0.0f;
#pragma unroll
                for (int sp = 0; sp < KSPLIT; sp++) {
                    a0 += __ldcg(&g_accum[sp][d][j]);
                    a1 += __ldcg(&g_accum[sp][d + 1][j]);
                }
                float x0 = a0 * inv + (1.0f - ETA) * X[d * NPTS + j];
                float x1 = a1 * inv + (1.0f - ETA) * X[(d + 1) * NPTS + j];
                Xn[d * NPTS + j] = x0;
                Xn[(d + 1) * NPTS + j] = x1;
                if (t < 2) {
                    g_v[d * NPTS + j] = __float2half(x0);
                    g_v[(d + 1) * NPTS + j] = __float2half(x1);
                    pk[q] = cvt_f16x2(x0 * SCALE, x1 * SCALE);
                }
            }
            if (t < 2)
                *reinterpret_cast<uint4*>(g_s + j * DIM + d0) =
                    make_uint4(pk[0], pk[1], pk[2], pk[3]);
        }
        if (t < 2) { tgt += GRID; grid_bar(tgt); }
    }

    // ---------------- epilogue: counter reset handshake ----------------
    __syncthreads();
    __threadfence();
    if (tid == 0) atomicAdd(&g_fin, 1u);
    if (gid == 0) {
        while (*(volatile unsigned*)&g_fin < GRID) __nanosleep(64);
        *(volatile unsigned*)&g_bar = 0;
        *(volatile unsigned*)&g_fin = 0;
        __threadfence();
    }
}

extern "C" void kernel_launch(void* const* d_in, const int* in_sizes, int n_in,
                              void* d_out, int out_size) {
    const float* x_in = (const float*)d_in[0];
    float* out = (float*)d_out;
    dim3 grid(JT, KSPLIT);
    ms_persist<<<grid, 128>>>(x_in, out);
}

// round 9
// speedup vs baseline: 1.0915x; 1.0205x over previous
#include <cuda_runtime.h>
#include <cuda_fp16.h>
#include <cstdint>

// Mean-shift as unnormalized attention, single persistent kernel (f16 path).
//   S = (sX)^T (sX), s^2 = 2*log2(e)  =>  P = ex2(S) = exp(2*x_i.x_j)
//   GEMM1 uses f16 accumulators: S lands directly in A-fragment layout,
//   so P = ex2.f16x2(S) in place (no cvt, no repack).
//   deg = P @ ones (tensor, fp32 accum);  O = P @ V (tensor, fp32 accum)
//   Xnew = eta*O/deg + (1-eta)X
// 2x2 warp tiling; 3-stage cp.async ring -> ONE __syncthreads per tile.

#define NPTS   9216
#define DIM    32
#define ETA    0.5f
#define SCALE  1.6986436f          // sqrt(2*log2(e))
#define TJ     64
#define TI     64
#define KSPLIT 4
#define JT     (NPTS / TJ)             // 144
#define NT     (NPTS / (TI * KSPLIT))  // 36 tiles per split
#define GRID   (JT * KSPLIT)           // 576
#define FRAME  (DIM * NPTS)

#define KST 80      // key row stride bytes (32 f16 + pad)
#define VST 144     // v row stride bytes (64 f16 + pad)
#define ONES2 0x3C003C00u

#define KBUF 5120               // TI * KST
#define VBUF 4608               // DIM * VST
#define SH_K 0                  // 3 x 5120 = 15360
#define SH_V (3 * KBUF)         // 3 x 4608 = 13824
#define SH_X 0                  // O exchange (8KB), aliases K staging
#define SH_XD 8192              // deg exchange (1KB)
#define SMEM_BYTES (3 * KBUF + 3 * VBUF)   // 29184

__device__ __align__(16) __half g_s[NPTS * DIM];  // [i][d], scaled, f16
__device__ __align__(16) __half g_v[DIM * NPTS];  // [d][i], f16
__device__ float g_accum[KSPLIT][DIM][NPTS];
__device__ float g_degp[KSPLIT][NPTS];
__device__ unsigned g_bar;
__device__ unsigned g_fin;

// ---------------- helpers ----------------
__device__ __forceinline__ uint32_t smem_u32(const void* p) {
    uint32_t a;
    asm("{ .reg .u64 t; cvta.to.shared.u64 t, %1; cvt.u32.u64 %0, t; }" : "=r"(a) : "l"(p));
    return a;
}
__device__ __forceinline__ void ldsm4(uint32_t* r, uint32_t a) {
    asm volatile("ldmatrix.sync.aligned.m8n8.x4.shared.b16 {%0,%1,%2,%3}, [%4];"
        : "=r"(r[0]), "=r"(r[1]), "=r"(r[2]), "=r"(r[3]) : "r"(a));
}
// fp32-accum mma (GEMM2 / deg)
__device__ __forceinline__ void mma16816(float* c, const uint32_t* a,
                                         uint32_t b0, uint32_t b1) {
    asm volatile("mma.sync.aligned.m16n8k16.row.col.f32.f16.f16.f32 "
        "{%0,%1,%2,%3}, {%4,%5,%6,%7}, {%8,%9}, {%0,%1,%2,%3};"
        : "+f"(c[0]), "+f"(c[1]), "+f"(c[2]), "+f"(c[3])
        : "r"(a[0]), "r"(a[1]), "r"(a[2]), "r"(a[3]), "r"(b0), "r"(b1));
}
// f16-accum mma (GEMM1): C/D are 2 b32 regs holding f16x2 in A-frag layout
__device__ __forceinline__ void mma16816h(uint32_t* c, const uint32_t* a,
                                          uint32_t b0, uint32_t b1) {
    asm volatile("mma.sync.aligned.m16n8k16.row.col.f16.f16.f16.f16 "
        "{%0,%1}, {%2,%3,%4,%5}, {%6,%7}, {%0,%1};"
        : "+r"(c[0]), "+r"(c[1])
        : "r"(a[0]), "r"(a[1]), "r"(a[2]), "r"(a[3]), "r"(b0), "r"(b1));
}
__device__ __forceinline__ uint32_t cvt_f16x2(float lo, float hi) {
    uint32_t r;
    asm("cvt.rn.f16x2.f32 %0, %1, %2;" : "=r"(r) : "f"(hi), "f"(lo));
    return r;
}
__device__ __forceinline__ uint32_t ex2_h2(uint32_t x) {
    uint32_t y;
    asm("ex2.approx.f16x2 %0, %1;" : "=r"(y) : "r"(x));
    return y;
}
#define CP16(dst, src) asm volatile("cp.async.cg.shared.global [%0], [%1], 16;" :: "r"(dst), "l"(src) : "memory")
#define CP_COMMIT()    asm volatile("cp.async.commit_group;" ::: "memory")
#define CP_WAIT0()     asm volatile("cp.async.wait_group 0;" ::: "memory")
#define CP_WAIT1()     asm volatile("cp.async.wait_group 1;" ::: "memory")

__device__ __forceinline__ void grid_bar(unsigned tgt) {
    __syncthreads();
    __threadfence();
    if (threadIdx.x == 0) {
        atomicAdd(&g_bar, 1u);
        while (*(volatile unsigned*)&g_bar < tgt) __nanosleep(32);
    }
    __syncthreads();
}

// Stage one 64-key K/V tile via cp.async (.cg: L2-only, avoids stale L1).
__device__ __forceinline__ void stage_tiles(uint32_t kdst, uint32_t vdst,
                                            int i0, int tid) {
    const char* ks = reinterpret_cast<const char*>(g_s) + (size_t)i0 * (DIM * 2);
#pragma unroll
    for (int v = 0; v < 2; v++) {
        int idx = v * 128 + tid, row = idx >> 2, c = idx & 3;
        CP16(kdst + row * KST + c * 16, ks + row * 64 + c * 16);
    }
    const char* vs = reinterpret_cast<const char*>(g_v) + (size_t)i0 * 2;
#pragma unroll
    for (int v = 0; v < 2; v++) {
        int idx = v * 128 + tid, row = idx >> 3, c = idx & 7;
        CP16(vdst + row * VST + c * 16, vs + (size_t)row * (NPTS * 2) + c * 16);
    }
}

__global__ void __launch_bounds__(128, 4)
ms_persist(const float* __restrict__ x_in, float* __restrict__ out) {
    __shared__ __align__(16) uint8_t sm[SMEM_BYTES];

    const int tid = threadIdx.x, w = tid >> 5, lane = tid & 31;
    const int wq = w >> 1, wk = w & 1;
    const int jt = blockIdx.x, split = blockIdx.y;
    const unsigned gid = (blockIdx.y * JT + blockIdx.x) * 128u + tid;
    const uint32_t smbase = smem_u32(sm);
    unsigned tgt = 0;

    // ---------------- phase 0: init (4 threads per pixel) ----------------
    if (gid < NPTS * 4u) {
        const int j = gid >> 2, d0 = (gid & 3) * 8;
        uint32_t pk[4];
#pragma unroll
        for (int q = 0; q < 4; q++) {
            int d = d0 + q * 2;
            float x0 = x_in[d * NPTS + j];
            float x1 = x_in[(d + 1) * NPTS + j];
            out[d * NPTS + j] = x0;
            out[(d + 1) * NPTS + j] = x1;
            g_v[d * NPTS + j] = __float2half(x0);
            g_v[(d + 1) * NPTS + j] = __float2half(x1);
            pk[q] = cvt_f16x2(x0 * SCALE, x1 * SCALE);
        }
        *reinterpret_cast<uint4*>(g_s + j * DIM + d0) =
            make_uint4(pk[0], pk[1], pk[2], pk[3]);
    }
    tgt += GRID; grid_bar(tgt);

    // hoisted ldsm addresses (buffer 0; add buf*KBUF / buf*VBUF)
    uint32_t ka0[4], va0[4];
#pragma unroll
    for (int nt = 0; nt < 4; nt++)
        ka0[nt] = smbase + SH_K + (wk * 32 + nt * 8 + (lane & 7)) * KST + (lane >> 3) * 16;
#pragma unroll
    for (int dt = 0; dt < 4; dt++)
        va0[dt] = smbase + SH_V + (dt * 8 + (lane & 7)) * VST + (wk * 32 + (lane >> 3) * 8) * 2;

    for (int t = 0; t < 3; t++) {
        // ---------------- attention phase ----------------
        const int j0 = jt * TJ;
        {
            const uint4* src = reinterpret_cast<const uint4*>(g_s) + j0 * 4;
#pragma unroll
            for (int v = 0; v < 2; v++) {
                int idx = v * 128 + tid, row = idx >> 2, c = idx & 3;
                uint4 val = __ldcg(&src[row * 4 + c]);
                *reinterpret_cast<uint4*>(&sm[SH_K + row * KST + c * 16]) = val;
            }
        }
        __syncthreads();
        // Q A-fragments: 2 mtiles (rows wq*32 + mt*16), k = 0..31
        uint32_t qa[16];
        {
            int m = lane >> 3, r = lane & 7;
#pragma unroll
            for (int mt = 0; mt < 2; mt++) {
                uint32_t base = smbase + SH_K +
                    (wq * 32 + mt * 16 + (m & 1) * 8 + r) * KST + (m >> 1) * 16;
                ldsm4(qa + mt * 8, base);
                ldsm4(qa + mt * 8 + 4, base + 32);
            }
        }
        __syncthreads();

        float O[32];
#pragma unroll
        for (int i = 0; i < 32; i++) O[i] = 0.0f;
        float dacc[8];
#pragma unroll
        for (int i = 0; i < 8; i++) dacc[i] = 0.0f;

        const int i00 = split * (NPTS / KSPLIT);
        stage_tiles(smbase + SH_K,        smbase + SH_V,        i00,      tid);
        CP_COMMIT();
        stage_tiles(smbase + SH_K + KBUF, smbase + SH_V + VBUF, i00 + TI, tid);
        CP_COMMIT();

        int buf = 0;
        for (int it = 0; it < NT; it++) {
            if (it + 1 < NT) { CP_WAIT1(); } else { CP_WAIT0(); }
            __syncthreads();
            if (it + 2 < NT) {
                int b2 = buf - 1; if (b2 < 0) b2 += 3;   // (it+2)%3
                stage_tiles(smbase + SH_K + b2 * KBUF, smbase + SH_V + b2 * VBUF,
                            i00 + (it + 2) * TI, tid);
                CP_COMMIT();
            }
            const uint32_t kofs = buf * KBUF, vofs = buf * VBUF;

            // GEMM1 (f16 accum): S[2 x 16 rows][32 keys] = Q x K^T
            // sc[mt*8 + nt*2 + {0,1}] : f16x2, C-frag == A-frag layout
            uint32_t sc[16];
#pragma unroll
            for (int x = 0; x < 16; x++) sc[x] = 0u;
#pragma unroll
            for (int nt = 0; nt < 4; nt++) {
                uint32_t kb[4];
                ldsm4(kb, ka0[nt] + kofs);
                mma16816h(&sc[nt * 2],     qa,      kb[0], kb[1]);
                mma16816h(&sc[nt * 2],     qa + 4,  kb[2], kb[3]);
                mma16816h(&sc[8 + nt * 2], qa + 8,  kb[0], kb[1]);
                mma16816h(&sc[8 + nt * 2], qa + 12, kb[2], kb[3]);
            }

            // P = ex2(S) in place -> GEMM2 A-fragments
#pragma unroll
            for (int x = 0; x < 16; x++) sc[x] = ex2_h2(sc[x]);

            // deg += P @ ones (fp32, tensor pipe, deterministic)
#pragma unroll
            for (int mt = 0; mt < 2; mt++) {
                mma16816(&dacc[mt * 4], &sc[mt * 8],     ONES2, ONES2);
                mma16816(&dacc[mt * 4], &sc[mt * 8 + 4], ONES2, ONES2);
            }

            // GEMM2: O[2 x 16 rows][32 d] += P x V  (V shared across mtiles)
#pragma unroll
            for (int dt = 0; dt < 4; dt++) {
                uint32_t vb[4];
                ldsm4(vb, va0[dt] + vofs);
                mma16816(&O[dt * 4],      &sc[0],  vb[0], vb[1]);
                mma16816(&O[dt * 4],      &sc[4],  vb[2], vb[3]);
                mma16816(&O[16 + dt * 4], &sc[8],  vb[0], vb[1]);
                mma16816(&O[16 + dt * 4], &sc[12], vb[2], vb[3]);
            }
            buf++; if (buf == 3) buf = 0;
        }

        // ---- cross-warp (wk) reduction of O and deg via smem ----
        __syncthreads();   // all warps done with K/V buffers (SH_X aliases them)
        if (wk == 1) {
#pragma unroll
            for (int r4 = 0; r4 < 8; r4++)
                *reinterpret_cast<float4*>(&sm[SH_X + wq * 4096 + r4 * 512 + lane * 16]) =
                    make_float4(O[r4 * 4], O[r4 * 4 + 1], O[r4 * 4 + 2], O[r4 * 4 + 3]);
            *reinterpret_cast<float2*>(&sm[SH_XD + wq * 512 + lane * 8]) =
                make_float2(dacc[0], dacc[2]);
            *reinterpret_cast<float2*>(&sm[SH_XD + wq * 512 + 256 + lane * 8]) =
                make_float2(dacc[4], dacc[6]);
        }
        __syncthreads();
        if (wk == 0) {
#pragma unroll
            for (int r4 = 0; r4 < 8; r4++) {
                float4 pv = *reinterpret_cast<const float4*>(
                    &sm[SH_X + wq * 4096 + r4 * 512 + lane * 16]);
                O[r4 * 4]     += pv.x;
                O[r4 * 4 + 1] += pv.y;
                O[r4 * 4 + 2] += pv.z;
                O[r4 * 4 + 3] += pv.w;
            }
            float2 p0 = *reinterpret_cast<const float2*>(&sm[SH_XD + wq * 512 + lane * 8]);
            float2 p1 = *reinterpret_cast<const float2*>(&sm[SH_XD + wq * 512 + 256 + lane * 8]);
            dacc[0] += p0.x; dacc[2] += p0.y;
            dacc[4] += p1.x; dacc[6] += p1.y;

#pragma unroll
            for (int mt = 0; mt < 2; mt++) {
                const int jj = j0 + wq * 32 + mt * 16 + (lane >> 2);
#pragma unroll
                for (int dt = 0; dt < 4; dt++) {
                    int d0 = dt * 8 + 2 * (lane & 3);
                    g_accum[split][d0][jj]         = O[mt * 16 + dt * 4 + 0];
                    g_accum[split][d0 + 1][jj]     = O[mt * 16 + dt * 4 + 1];
                    g_accum[split][d0][jj + 8]     = O[mt * 16 + dt * 4 + 2];
                    g_accum[split][d0 + 1][jj + 8] = O[mt * 16 + dt * 4 + 3];
                }
                if ((lane & 3) == 0) {
                    g_degp[split][jj]     = dacc[mt * 4 + 0];
                    g_degp[split][jj + 8] = dacc[mt * 4 + 2];
                }
            }
        }
        tgt += GRID; grid_bar(tgt);

        // ---------------- reduce phase (4 threads per pixel) ----------------
        if (gid < NPTS * 4u) {
            const int j = gid >> 2, d0 = (gid & 3) * 8;
            float deg = 0.0f;
#pragma unroll
            for (int sp = 0; sp < KSPLIT; sp++) deg += __ldcg(&g_degp[sp][j]);
            const float inv = ETA / deg;
            const float* X  = out + (size_t)t * FRAME;
            float*       Xn = out + (size_t)(t + 1) * FRAME;
            uint32_t pk[4];
#pragma unroll
            for (int q = 0; q < 4; q++) {
                int d = d0 + q * 2;
                float a0 = 0.0f, a1 = 0.0f;
#pragma unroll
                for (int sp = 0; sp < KSPLIT; sp++) {
                    a0 += __ldcg(&g_accum[sp][d][j]);
                    a1 += __ldcg(&g_accum[sp][d + 1][j]);
                }
                float x0 = a0 * inv + (1.0f - ETA) * X[d * NPTS + j];
                float x1 = a1 * inv + (1.0f - ETA) * X[(d + 1) * NPTS + j];
                Xn[d * NPTS + j] = x0;
                Xn[(d + 1) * NPTS + j] = x1;
                if (t < 2) {
                    g_v[d * NPTS + j] = __float2half(x0);
                    g_v[(d + 1) * NPTS + j] = __float2half(x1);
                    pk[q] = cvt_f16x2(x0 * SCALE, x1 * SCALE);
                }
            }
            if (t < 2)
                *reinterpret_cast<uint4*>(g_s + j * DIM + d0) =
                    make_uint4(pk[0], pk[1], pk[2], pk[3]);
        }
        if (t < 2) { tgt += GRID; grid_bar(tgt); }
    }

    // ---------------- epilogue: counter reset handshake ----------------
    __syncthreads();
    __threadfence();
    if (tid == 0) atomicAdd(&g_fin, 1u);
    if (gid == 0) {
        while (*(volatile unsigned*)&g_fin < GRID) __nanosleep(64);
        *(volatile unsigned*)&g_bar = 0;
        *(volatile unsigned*)&g_fin = 0;
        __threadfence();
    }
}

extern "C" void kernel_launch(void* const* d_in, const int* in_sizes, int n_in,
                              void* d_out, int out_size) {
    const float* x_in = (const float*)d_in[0];
    float* out = (float*)d_out;
    dim3 grid(JT, KSPLIT);
    ms_persist<<<grid, 128>>>(x_in, out);
}